// round 9
// baseline (speedup 1.0000x reference)
#include <cuda_runtime.h>
#include <math.h>

#define MPTS 32
#define PPB  4     // pillars per block, 1 warp per pillar (128 threads)

// Coalesced per-lane constant arrays (lane stride 16B within each array):
// g_a[c][lane] = (A_c[2t], A_c[2t], A_c[2t+1], A_c[2t+1])  -- pre-duplicated
//                for direct use as two f32x2 coefficient registers.
// g_m[0][lane] = (M4.x, M4.y, M5.x, M5.y)
// g_m[1][lane] = (M6.x, M6.y, C7.x, C7.y)
// g_m[2][lane] = (C8.x, C8.y, C9.x, C9.y)
// g_m[3][lane] = (bp.x, bp.y, gb.x, gb.y)
__device__ float4 g_a[4][32];
__device__ float4 g_m[4][32];

__device__ __forceinline__ float gelu_exact(float x) {
    return 0.5f * x * (1.0f + erff(x * 0.70710678118654752f));
}

// Branchless fast GELU: erf via Abramowitz-Stegun 7.1.26 (|err| < 1.5e-7).
// Tails are exact: exp2 underflows to 0 => gelu -> x (x>0) / 0 (x<0).
__device__ __forceinline__ float gelu_fast(float x) {
    float t = fabsf(x) * 0.70710678118654752f;
    float kd = fmaf(0.3275911f, t, 1.0f);
    float k;
    asm("rcp.approx.f32 %0, %1;" : "=f"(k) : "f"(kd));
    float p = fmaf(1.061405429f, k, -1.453152027f);
    p = fmaf(p, k, 1.421413741f);
    p = fmaf(p, k, -0.284496736f);
    p = fmaf(p, k, 0.254829592f);
    p = p * k;
    float e = exp2f(-t * t * 1.4426950408889634f);   // exp(-t^2)
    float erf_abs = fmaf(-p, e, 1.0f);                // erf(|x|/sqrt2)
    float erf_x = copysignf(erf_abs, x);
    float hx = 0.5f * x;
    return fmaf(hx, erf_x, hx);                       // 0.5*x*(1+erf)
}

typedef unsigned long long u64;
__device__ __forceinline__ u64 fma2(u64 a, u64 b, u64 c) {
    u64 d; asm("fma.rn.f32x2 %0, %1, %2, %3;" : "=l"(d) : "l"(a), "l"(b), "l"(c));
    return d;
}
__device__ __forceinline__ u64 mul2(u64 a, u64 b) {
    u64 d; asm("mul.rn.f32x2 %0, %1, %2;" : "=l"(d) : "l"(a), "l"(b));
    return d;
}
__device__ __forceinline__ void unpack2(u64 v, float& lo, float& hi) {
    asm("mov.b64 {%0, %1}, %2;" : "=f"(lo), "=f"(hi) : "l"(v));
}

// Fold BN into W; exploit affine structure of augmented channels:
//   x[m,o] = f0*(w0+w4+w7)+f1*(w1+w5+w8)+f2*(w2+w6+w9)+f3*w3
//            - mx*w4-my*w5-mz*w6 - px*w7-py*w8-pz*w9 + bias
// Voxel-center terms folded: -px*w7 = cx*(-0.2*w7) - 0.1*w7 (offset into bp').
// One thread per channel PAIR t (channels 2t, 2t+1).
__global__ void pfn_precompute(const float* __restrict__ W,
                               const float* __restrict__ gamma,
                               const float* __restrict__ beta,
                               const float* __restrict__ rmean,
                               const float* __restrict__ rvar) {
    int t = threadIdx.x;
    if (t >= 32) return;
    float A[2][4], M[2][3], C[2][3], BP[2], GB[2];
#pragma unroll
    for (int h = 0; h < 2; h++) {
        int o = 2 * t + h;
        float s  = rsqrtf(rvar[o] + 1e-3f) * gamma[o];
        float bp = beta[o] - rmean[o] * s;          // true BN bias
        float w[10];
#pragma unroll
        for (int c = 0; c < 10; c++) w[c] = W[o * 10 + c] * s;
        A[h][0] = w[0] + w[4] + w[7];
        A[h][1] = w[1] + w[5] + w[8];
        A[h][2] = w[2] + w[6] + w[9];
        A[h][3] = w[3];
        M[h][0] = -w[4]; M[h][1] = -w[5]; M[h][2] = -w[6];
        C[h][0] = -0.2f * w[7]; C[h][1] = -0.2f * w[8]; C[h][2] = -4.0f * w[9];
        BP[h] = bp - 0.1f * w[7] + 39.9f * w[8] + 1.0f * w[9];
        GB[h] = gelu_exact(bp);
    }
#pragma unroll
    for (int c = 0; c < 4; c++)
        g_a[c][t] = make_float4(A[0][c], A[0][c], A[1][c], A[1][c]);
    g_m[0][t] = make_float4(M[0][0], M[1][0], M[0][1], M[1][1]);
    g_m[1][t] = make_float4(M[0][2], M[1][2], C[0][0], C[1][0]);
    g_m[2][t] = make_float4(C[0][1], C[1][1], C[0][2], C[1][2]);
    g_m[3][t] = make_float4(BP[0], BP[1], GB[0], GB[1]);
}

__global__ __launch_bounds__(PPB * 32, 12)
void pfn_main(const float4* __restrict__ feats,      // [N,32] float4
              const int*    __restrict__ num_points,  // [N]
              const int4*   __restrict__ coors,       // [N] (z,y,x,_)
              float*        __restrict__ out,         // [N,64]
              int N) {
    __shared__ float sdat[PPB][4][MPTS];   // transposed SoA per pillar

    const int lp   = threadIdx.x >> 5;
    const int lane = threadIdx.x & 31;
    const int p    = blockIdx.x * PPB + lp;
    if (p >= N) return;                     // whole warp exits together

    const int K = num_points[p];

    // ---- stage: coalesced 512B row load per warp ----
    float4 row = feats[(size_t)p * MPTS + lane];

    // mean over ALL 32 raw rows (reference sums unmasked garbage too), / K
    float sx = row.x, sy = row.y, sz = row.z;
#pragma unroll
    for (int off = 16; off; off >>= 1) {
        sx += __shfl_xor_sync(0xffffffffu, sx, off);
        sy += __shfl_xor_sync(0xffffffffu, sy, off);
        sz += __shfl_xor_sync(0xffffffffu, sz, off);
    }
    float rK;
    asm("rcp.approx.f32 %0, %1;" : "=f"(rK) : "f"((float)K));
    const float mx = sx * rK, my = sy * rK, mz = sz * rK;

    // pad invalid rows with a COPY of row 0 (K>=1 always): duplicates a valid
    // point's d-value, so min/max are unaffected by padding.
    float r0x = __shfl_sync(0xffffffffu, row.x, 0);
    float r0y = __shfl_sync(0xffffffffu, row.y, 0);
    float r0z = __shfl_sync(0xffffffffu, row.z, 0);
    float r0w = __shfl_sync(0xffffffffu, row.w, 0);
    if (lane >= K) { row.x = r0x; row.y = r0y; row.z = r0z; row.w = r0w; }
    sdat[lp][0][lane] = row.x;
    sdat[lp][1][lane] = row.y;
    sdat[lp][2][lane] = row.z;
    sdat[lp][3][lane] = row.w;
    __syncwarp();

    // ---- per-thread constants: channels (2*lane, 2*lane+1) ----
    // Pre-duplicated packed coefficients, loaded as two u64 halves of float4.
    const ulonglong2 A0 = *(const ulonglong2*)&g_a[0][lane];
    const ulonglong2 A1 = *(const ulonglong2*)&g_a[1][lane];
    const ulonglong2 A2 = *(const ulonglong2*)&g_a[2][lane];
    const ulonglong2 A3 = *(const ulonglong2*)&g_a[3][lane];
    const u64 a0c0 = A0.x, a0c1 = A0.y;
    const u64 a1c0 = A1.x, a1c1 = A1.y;
    const u64 a2c0 = A2.x, a2c1 = A2.y;
    const u64 a3c0 = A3.x, a3c1 = A3.y;
    const float4 m0 = g_m[0][lane];   // (M4.x, M4.y, M5.x, M5.y)
    const float4 m1 = g_m[1][lane];   // (M6.x, M6.y, C7.x, C7.y)
    const float4 m2 = g_m[2][lane];   // (C8.x, C8.y, C9.x, C9.y)
    const float4 m3 = g_m[3][lane];   // (bp.x, bp.y, gb.x, gb.y)

    const int4 cr = coors[p];
    const float czf = (float)cr.x;   // coors[:,0] = cz
    const float cyf = (float)cr.y;   // coors[:,1] = cy
    const float cxf = (float)cr.z;   // coors[:,2] = cx

    float cst0 = m3.x, cst1 = m3.y;
    cst0 = fmaf(mx,  m0.x, cst0); cst1 = fmaf(mx,  m0.y, cst1);
    cst0 = fmaf(my,  m0.z, cst0); cst1 = fmaf(my,  m0.w, cst1);
    cst0 = fmaf(mz,  m1.x, cst0); cst1 = fmaf(mz,  m1.y, cst1);
    cst0 = fmaf(cxf, m1.z, cst0); cst1 = fmaf(cxf, m1.w, cst1);
    cst0 = fmaf(cyf, m2.x, cst0); cst1 = fmaf(cyf, m2.y, cst1);
    cst0 = fmaf(czf, m2.z, cst0); cst1 = fmaf(czf, m2.w, cst1);

    const float INF = 3.402823466e38f;
    float mx0a = -INF, mx0b = -INF, mn0a = INF, mn0b = INF;   // channel 0
    float mx1a = -INF, mx1b = -INF, mn1a = INF, mn1b = INF;   // channel 1

    const int T = (K + 3) >> 2;
#pragma unroll 2
    for (int i = 0; i < T; i++) {
        // 4 points of each component as (m,m+1),(m+2,m+3) f32x2 pairs
        ulonglong2 X  = *(const ulonglong2*)&sdat[lp][0][4 * i];
        ulonglong2 Y  = *(const ulonglong2*)&sdat[lp][1][4 * i];
        ulonglong2 Z  = *(const ulonglong2*)&sdat[lp][2][4 * i];
        ulonglong2 Wv = *(const ulonglong2*)&sdat[lp][3][4 * i];

        // channel 0
        u64 d0a = fma2(X.x, a0c0, fma2(Y.x, a1c0, fma2(Z.x, a2c0, mul2(Wv.x, a3c0))));
        u64 d0b = fma2(X.y, a0c0, fma2(Y.y, a1c0, fma2(Z.y, a2c0, mul2(Wv.y, a3c0))));
        // channel 1
        u64 d1a = fma2(X.x, a0c1, fma2(Y.x, a1c1, fma2(Z.x, a2c1, mul2(Wv.x, a3c1))));
        u64 d1b = fma2(X.y, a0c1, fma2(Y.y, a1c1, fma2(Z.y, a2c1, mul2(Wv.y, a3c1))));

        float l, h;
        unpack2(d0a, l, h); mx0a = fmaxf(mx0a, l); mn0a = fminf(mn0a, l);
                            mx0b = fmaxf(mx0b, h); mn0b = fminf(mn0b, h);
        unpack2(d0b, l, h); mx0a = fmaxf(mx0a, l); mn0a = fminf(mn0a, l);
                            mx0b = fmaxf(mx0b, h); mn0b = fminf(mn0b, h);
        unpack2(d1a, l, h); mx1a = fmaxf(mx1a, l); mn1a = fminf(mn1a, l);
                            mx1b = fmaxf(mx1b, h); mn1b = fminf(mn1b, h);
        unpack2(d1b, l, h); mx1a = fmaxf(mx1a, l); mn1a = fminf(mn1a, l);
                            mx1b = fmaxf(mx1b, h); mn1b = fminf(mn1b, h);
    }

    const float dmax0 = fmaxf(mx0a, mx0b), dmin0 = fminf(mn0a, mn0b);
    const float dmax1 = fmaxf(mx1a, mx1b), dmin1 = fminf(mn1a, mn1b);

    // gelu unimodal => max over gelu = max(gelu(min), gelu(max));
    // masked rows contribute exactly gelu(true bias).
    float r0 = fmaxf(gelu_fast(dmax0 + cst0), gelu_fast(dmin0 + cst0));
    float r1 = fmaxf(gelu_fast(dmax1 + cst1), gelu_fast(dmin1 + cst1));
    r0 = (K < MPTS) ? fmaxf(r0, m3.z) : r0;
    r1 = (K < MPTS) ? fmaxf(r1, m3.w) : r1;

    *(float2*)&out[(size_t)p * 64 + 2 * lane] = make_float2(r0, r1);
}

extern "C" void kernel_launch(void* const* d_in, const int* in_sizes, int n_in,
                              void* d_out, int out_size) {
    const float* features   = (const float*)d_in[0];
    const int*   num_points = (const int*)d_in[1];
    const int*   coors      = (const int*)d_in[2];
    const float* W          = (const float*)d_in[3];
    const float* gamma      = (const float*)d_in[4];
    const float* beta       = (const float*)d_in[5];
    const float* rmean      = (const float*)d_in[6];
    const float* rvar       = (const float*)d_in[7];
    float* out = (float*)d_out;

    const int N = in_sizes[0] / (MPTS * 4);

    pfn_precompute<<<1, 32>>>(W, gamma, beta, rmean, rvar);

    int blocks = (N + PPB - 1) / PPB;
    pfn_main<<<blocks, PPB * 32>>>((const float4*)features, num_points,
                                   (const int4*)coors, out, N);
}

// round 11
// speedup vs baseline: 1.1149x; 1.1149x over previous
#include <cuda_runtime.h>
#include <math.h>

#define MPTS 32
#define PPB  4     // pillars per block, 1 warp per pillar (128 threads)

// Coalesced per-lane constant arrays (lane stride 16B within each array):
// g_a[c][lane] = (A_c[2t], A_c[2t], A_c[2t+1], A_c[2t+1])  -- pre-duplicated
//                so the two u64 halves ARE the packed f32x2 coefficients.
// g_m[0][lane] = (M4.x, M4.y, M5.x, M5.y)
// g_m[1][lane] = (M6.x, M6.y, C7.x, C7.y)
// g_m[2][lane] = (C8.x, C8.y, C9.x, C9.y)
// g_m[3][lane] = (bp.x, bp.y, gb.x, gb.y)
__device__ float4 g_a[4][32];
__device__ float4 g_m[4][32];

__device__ __forceinline__ float gelu_exact(float x) {
    return 0.5f * x * (1.0f + erff(x * 0.70710678118654752f));
}

// Branchless fast GELU: erf via Abramowitz-Stegun 7.1.26 (|err| < 1.5e-7).
// Tails are exact: exp2 underflows to 0 => gelu -> x (x>0) / 0 (x<0).
__device__ __forceinline__ float gelu_fast(float x) {
    float t = fabsf(x) * 0.70710678118654752f;
    float kd = fmaf(0.3275911f, t, 1.0f);
    float k;
    asm("rcp.approx.f32 %0, %1;" : "=f"(k) : "f"(kd));
    float p = fmaf(1.061405429f, k, -1.453152027f);
    p = fmaf(p, k, 1.421413741f);
    p = fmaf(p, k, -0.284496736f);
    p = fmaf(p, k, 0.254829592f);
    p = p * k;
    float e = exp2f(-t * t * 1.4426950408889634f);   // exp(-t^2)
    float erf_abs = fmaf(-p, e, 1.0f);                // erf(|x|/sqrt2)
    float erf_x = copysignf(erf_abs, x);
    float hx = 0.5f * x;
    return fmaf(hx, erf_x, hx);                       // 0.5*x*(1+erf)
}

typedef unsigned long long u64;
__device__ __forceinline__ u64 fma2(u64 a, u64 b, u64 c) {
    u64 d; asm("fma.rn.f32x2 %0, %1, %2, %3;" : "=l"(d) : "l"(a), "l"(b), "l"(c));
    return d;
}
__device__ __forceinline__ u64 mul2(u64 a, u64 b) {
    u64 d; asm("mul.rn.f32x2 %0, %1, %2;" : "=l"(d) : "l"(a), "l"(b));
    return d;
}
__device__ __forceinline__ void unpack2(u64 v, float& lo, float& hi) {
    asm("mov.b64 {%0, %1}, %2;" : "=f"(lo), "=f"(hi) : "l"(v));
}

// Fold BN into W; exploit affine structure of augmented channels:
//   x[m,o] = f0*(w0+w4+w7)+f1*(w1+w5+w8)+f2*(w2+w6+w9)+f3*w3
//            - mx*w4-my*w5-mz*w6 - px*w7-py*w8-pz*w9 + bias
// Voxel-center terms folded: -px*w7 = cx*(-0.2*w7) - 0.1*w7 (offset into bp').
// One thread per channel PAIR t (channels 2t, 2t+1).
__global__ void pfn_precompute(const float* __restrict__ W,
                               const float* __restrict__ gamma,
                               const float* __restrict__ beta,
                               const float* __restrict__ rmean,
                               const float* __restrict__ rvar) {
    int t = threadIdx.x;
    if (t >= 32) return;
    float A[2][4], M[2][3], C[2][3], BP[2], GB[2];
#pragma unroll
    for (int h = 0; h < 2; h++) {
        int o = 2 * t + h;
        float s  = rsqrtf(rvar[o] + 1e-3f) * gamma[o];
        float bp = beta[o] - rmean[o] * s;          // true BN bias
        float w[10];
#pragma unroll
        for (int c = 0; c < 10; c++) w[c] = W[o * 10 + c] * s;
        A[h][0] = w[0] + w[4] + w[7];
        A[h][1] = w[1] + w[5] + w[8];
        A[h][2] = w[2] + w[6] + w[9];
        A[h][3] = w[3];
        M[h][0] = -w[4]; M[h][1] = -w[5]; M[h][2] = -w[6];
        C[h][0] = -0.2f * w[7]; C[h][1] = -0.2f * w[8]; C[h][2] = -4.0f * w[9];
        BP[h] = bp - 0.1f * w[7] + 39.9f * w[8] + 1.0f * w[9];
        GB[h] = gelu_exact(bp);
    }
#pragma unroll
    for (int c = 0; c < 4; c++)
        g_a[c][t] = make_float4(A[0][c], A[0][c], A[1][c], A[1][c]);
    g_m[0][t] = make_float4(M[0][0], M[1][0], M[0][1], M[1][1]);
    g_m[1][t] = make_float4(M[0][2], M[1][2], C[0][0], C[1][0]);
    g_m[2][t] = make_float4(C[0][1], C[1][1], C[0][2], C[1][2]);
    g_m[3][t] = make_float4(BP[0], BP[1], GB[0], GB[1]);
}

__global__ __launch_bounds__(PPB * 32)
void pfn_main(const float4* __restrict__ feats,      // [N,32] float4
              const int*    __restrict__ num_points,  // [N]
              const int4*   __restrict__ coors,       // [N] (z,y,x,_)
              float*        __restrict__ out,         // [N,64]
              int N) {
    __shared__ float sdat[PPB][4][MPTS];   // transposed SoA per pillar

    const int lp   = threadIdx.x >> 5;
    const int lane = threadIdx.x & 31;
    const int p    = blockIdx.x * PPB + lp;
    if (p >= N) return;                     // whole warp exits together

    const int K = num_points[p];

    // ---- stage: coalesced 512B row load per warp ----
    float4 row = feats[(size_t)p * MPTS + lane];

    // mean over ALL 32 raw rows (reference sums unmasked garbage too), / K
    float sx = row.x, sy = row.y, sz = row.z;
#pragma unroll
    for (int off = 16; off; off >>= 1) {
        sx += __shfl_xor_sync(0xffffffffu, sx, off);
        sy += __shfl_xor_sync(0xffffffffu, sy, off);
        sz += __shfl_xor_sync(0xffffffffu, sz, off);
    }
    float rK;
    asm("rcp.approx.f32 %0, %1;" : "=f"(rK) : "f"((float)K));
    const float mx = sx * rK, my = sy * rK, mz = sz * rK;

    // pad invalid rows with a COPY of row 0 (K>=1 always): duplicates a valid
    // point's d-value, so min/max are unaffected by padding.
    float r0x = __shfl_sync(0xffffffffu, row.x, 0);
    float r0y = __shfl_sync(0xffffffffu, row.y, 0);
    float r0z = __shfl_sync(0xffffffffu, row.z, 0);
    float r0w = __shfl_sync(0xffffffffu, row.w, 0);
    if (lane >= K) { row.x = r0x; row.y = r0y; row.z = r0z; row.w = r0w; }
    sdat[lp][0][lane] = row.x;
    sdat[lp][1][lane] = row.y;
    sdat[lp][2][lane] = row.z;
    sdat[lp][3][lane] = row.w;
    __syncwarp();

    // ---- per-thread constants: channels (2*lane, 2*lane+1) ----
    // Pre-duplicated packed coefficients: each float4 load yields the two
    // f32x2 coefficient registers directly (no pack MOVs).
    const ulonglong2 A0 = *(const ulonglong2*)&g_a[0][lane];
    const ulonglong2 A1 = *(const ulonglong2*)&g_a[1][lane];
    const ulonglong2 A2 = *(const ulonglong2*)&g_a[2][lane];
    const ulonglong2 A3 = *(const ulonglong2*)&g_a[3][lane];
    const u64 a0c0 = A0.x, a0c1 = A0.y;
    const u64 a1c0 = A1.x, a1c1 = A1.y;
    const u64 a2c0 = A2.x, a2c1 = A2.y;
    const u64 a3c0 = A3.x, a3c1 = A3.y;
    const float4 m0 = g_m[0][lane];   // (M4.x, M4.y, M5.x, M5.y)
    const float4 m1 = g_m[1][lane];   // (M6.x, M6.y, C7.x, C7.y)
    const float4 m2 = g_m[2][lane];   // (C8.x, C8.y, C9.x, C9.y)
    const float4 m3 = g_m[3][lane];   // (bp.x, bp.y, gb.x, gb.y)

    const int4 cr = coors[p];
    const float czf = (float)cr.x;   // coors[:,0] = cz
    const float cyf = (float)cr.y;   // coors[:,1] = cy
    const float cxf = (float)cr.z;   // coors[:,2] = cx

    float cst0 = m3.x, cst1 = m3.y;
    cst0 = fmaf(mx,  m0.x, cst0); cst1 = fmaf(mx,  m0.y, cst1);
    cst0 = fmaf(my,  m0.z, cst0); cst1 = fmaf(my,  m0.w, cst1);
    cst0 = fmaf(mz,  m1.x, cst0); cst1 = fmaf(mz,  m1.y, cst1);
    cst0 = fmaf(cxf, m1.z, cst0); cst1 = fmaf(cxf, m1.w, cst1);
    cst0 = fmaf(cyf, m2.x, cst0); cst1 = fmaf(cyf, m2.y, cst1);
    cst0 = fmaf(czf, m2.z, cst0); cst1 = fmaf(czf, m2.w, cst1);

    const float INF = 3.402823466e38f;
    float mx0a = -INF, mx0b = -INF, mn0a = INF, mn0b = INF;   // channel 0
    float mx1a = -INF, mx1b = -INF, mn1a = INF, mn1b = INF;   // channel 1

    const int T = (K + 3) >> 2;
#pragma unroll 2
    for (int i = 0; i < T; i++) {
        // 4 points of each component as (m,m+1),(m+2,m+3) f32x2 pairs
        ulonglong2 X  = *(const ulonglong2*)&sdat[lp][0][4 * i];
        ulonglong2 Y  = *(const ulonglong2*)&sdat[lp][1][4 * i];
        ulonglong2 Z  = *(const ulonglong2*)&sdat[lp][2][4 * i];
        ulonglong2 Wv = *(const ulonglong2*)&sdat[lp][3][4 * i];

        // channel 0
        u64 d0a = fma2(X.x, a0c0, fma2(Y.x, a1c0, fma2(Z.x, a2c0, mul2(Wv.x, a3c0))));
        u64 d0b = fma2(X.y, a0c0, fma2(Y.y, a1c0, fma2(Z.y, a2c0, mul2(Wv.y, a3c0))));
        // channel 1
        u64 d1a = fma2(X.x, a0c1, fma2(Y.x, a1c1, fma2(Z.x, a2c1, mul2(Wv.x, a3c1))));
        u64 d1b = fma2(X.y, a0c1, fma2(Y.y, a1c1, fma2(Z.y, a2c1, mul2(Wv.y, a3c1))));

        float l, h;
        unpack2(d0a, l, h); mx0a = fmaxf(mx0a, l); mn0a = fminf(mn0a, l);
                            mx0b = fmaxf(mx0b, h); mn0b = fminf(mn0b, h);
        unpack2(d0b, l, h); mx0a = fmaxf(mx0a, l); mn0a = fminf(mn0a, l);
                            mx0b = fmaxf(mx0b, h); mn0b = fminf(mn0b, h);
        unpack2(d1a, l, h); mx1a = fmaxf(mx1a, l); mn1a = fminf(mn1a, l);
                            mx1b = fmaxf(mx1b, h); mn1b = fminf(mn1b, h);
        unpack2(d1b, l, h); mx1a = fmaxf(mx1a, l); mn1a = fminf(mn1a, l);
                            mx1b = fmaxf(mx1b, h); mn1b = fminf(mn1b, h);
    }

    const float dmax0 = fmaxf(mx0a, mx0b), dmin0 = fminf(mn0a, mn0b);
    const float dmax1 = fmaxf(mx1a, mx1b), dmin1 = fminf(mn1a, mn1b);

    // gelu unimodal => max over gelu = max(gelu(min), gelu(max));
    // masked rows contribute exactly gelu(true bias).
    float r0 = fmaxf(gelu_fast(dmax0 + cst0), gelu_fast(dmin0 + cst0));
    float r1 = fmaxf(gelu_fast(dmax1 + cst1), gelu_fast(dmin1 + cst1));
    r0 = (K < MPTS) ? fmaxf(r0, m3.z) : r0;
    r1 = (K < MPTS) ? fmaxf(r1, m3.w) : r1;

    *(float2*)&out[(size_t)p * 64 + 2 * lane] = make_float2(r0, r1);
}

extern "C" void kernel_launch(void* const* d_in, const int* in_sizes, int n_in,
                              void* d_out, int out_size) {
    const float* features   = (const float*)d_in[0];
    const int*   num_points = (const int*)d_in[1];
    const int*   coors      = (const int*)d_in[2];
    const float* W          = (const float*)d_in[3];
    const float* gamma      = (const float*)d_in[4];
    const float* beta       = (const float*)d_in[5];
    const float* rmean      = (const float*)d_in[6];
    const float* rvar       = (const float*)d_in[7];
    float* out = (float*)d_out;

    const int N = in_sizes[0] / (MPTS * 4);

    pfn_precompute<<<1, 32>>>(W, gamma, beta, rmean, rvar);

    int blocks = (N + PPB - 1) / PPB;
    pfn_main<<<blocks, PPB * 32>>>((const float4*)features, num_points,
                                   (const int4*)coors, out, N);
}

// round 13
// speedup vs baseline: 1.1584x; 1.0390x over previous
#include <cuda_runtime.h>
#include <math.h>

#define MPTS 32
#define PPB  2     // pillars per block, 1 warp per pillar (64 threads)

// Precomputed constants, packed per channel-pair t: (val[2t], val[2t+1])
__device__ float2 g_pA[4][32];   // folded A0..A3 (dot coefficients)
__device__ float2 g_pW[6][32];   // -W4..-W6 (mean terms), C7..C9 (coor terms)
__device__ float2 g_pbp[32];     // cst-chain bias (voxel offsets folded in)
__device__ float2 g_pgb[32];     // gelu(true bias) = masked-row contribution

__device__ __forceinline__ float gelu_exact(float x) {
    return 0.5f * x * (1.0f + erff(x * 0.70710678118654752f));
}

// Branchless fast GELU: erf via Abramowitz-Stegun 7.1.26 (|err| < 1.5e-7).
// Tails are exact: exp2 underflows to 0 => gelu -> x (x>0) / 0 (x<0).
__device__ __forceinline__ float gelu_fast(float x) {
    float t = fabsf(x) * 0.70710678118654752f;
    float kd = fmaf(0.3275911f, t, 1.0f);
    float k;
    asm("rcp.approx.f32 %0, %1;" : "=f"(k) : "f"(kd));
    float p = fmaf(1.061405429f, k, -1.453152027f);
    p = fmaf(p, k, 1.421413741f);
    p = fmaf(p, k, -0.284496736f);
    p = fmaf(p, k, 0.254829592f);
    p = p * k;
    float e = exp2f(-t * t * 1.4426950408889634f);   // exp(-t^2)
    float erf_abs = fmaf(-p, e, 1.0f);                // erf(|x|/sqrt2)
    float erf_x = copysignf(erf_abs, x);
    float hx = 0.5f * x;
    return fmaf(hx, erf_x, hx);                       // 0.5*x*(1+erf)
}

typedef unsigned long long u64;
__device__ __forceinline__ u64 fma2(u64 a, u64 b, u64 c) {
    u64 d; asm("fma.rn.f32x2 %0, %1, %2, %3;" : "=l"(d) : "l"(a), "l"(b), "l"(c));
    return d;
}
__device__ __forceinline__ u64 mul2(u64 a, u64 b) {
    u64 d; asm("mul.rn.f32x2 %0, %1, %2;" : "=l"(d) : "l"(a), "l"(b));
    return d;
}
__device__ __forceinline__ u64 pack2(float lo, float hi) {
    u64 d; asm("mov.b64 %0, {%1, %2};" : "=l"(d) : "f"(lo), "f"(hi));
    return d;
}
__device__ __forceinline__ void unpack2(u64 v, float& lo, float& hi) {
    asm("mov.b64 {%0, %1}, %2;" : "=f"(lo), "=f"(hi) : "l"(v));
}

// Fold BN into W; exploit affine structure of augmented channels:
//   x[m,o] = f0*(w0+w4+w7)+f1*(w1+w5+w8)+f2*(w2+w6+w9)+f3*w3
//            - mx*w4-my*w5-mz*w6 - px*w7-py*w8-pz*w9 + bias
// Voxel-center terms folded: -px*w7 = cx*(-0.2*w7) - 0.1*w7 (offset into bp').
__global__ void pfn_precompute(const float* __restrict__ W,
                               const float* __restrict__ gamma,
                               const float* __restrict__ beta,
                               const float* __restrict__ rmean,
                               const float* __restrict__ rvar) {
    int o = threadIdx.x;
    if (o >= 64) return;
    float s  = rsqrtf(rvar[o] + 1e-3f) * gamma[o];
    float bp = beta[o] - rmean[o] * s;      // true BN bias (masked-row value)
    float w[10];
#pragma unroll
    for (int c = 0; c < 10; c++) w[c] = W[o * 10 + c] * s;
    int t = o >> 1, h = o & 1;
    ((float*)&g_pA[0][t])[h] = w[0] + w[4] + w[7];
    ((float*)&g_pA[1][t])[h] = w[1] + w[5] + w[8];
    ((float*)&g_pA[2][t])[h] = w[2] + w[6] + w[9];
    ((float*)&g_pA[3][t])[h] = w[3];
    ((float*)&g_pW[0][t])[h] = -w[4];
    ((float*)&g_pW[1][t])[h] = -w[5];
    ((float*)&g_pW[2][t])[h] = -w[6];
    ((float*)&g_pW[3][t])[h] = -0.2f * w[7];
    ((float*)&g_pW[4][t])[h] = -0.2f * w[8];
    ((float*)&g_pW[5][t])[h] = -4.0f * w[9];
    ((float*)&g_pbp[t])[h] = bp - 0.1f * w[7] + 39.9f * w[8] + 1.0f * w[9];
    ((float*)&g_pgb[t])[h] = gelu_exact(bp);
}

__global__ __launch_bounds__(PPB * 32)
void pfn_main(const float4* __restrict__ feats,      // [N,32] float4
              const int*    __restrict__ num_points,  // [N]
              const int4*   __restrict__ coors,       // [N] (z,y,x,_)
              float*        __restrict__ out,         // [N,64]
              int N) {
    __shared__ float sdat[PPB][4][MPTS];   // transposed SoA per pillar

    const int lp   = threadIdx.x >> 5;
    const int lane = threadIdx.x & 31;
    const int p    = blockIdx.x * PPB + lp;
    if (p >= N) return;                     // whole warp exits together

    const int K = num_points[p];

    // ---- stage: coalesced 512B row load per warp ----
    float4 row = feats[(size_t)p * MPTS + lane];

    // mean over ALL 32 raw rows (reference sums unmasked garbage too), / K
    float sx = row.x, sy = row.y, sz = row.z;
#pragma unroll
    for (int off = 16; off; off >>= 1) {
        sx += __shfl_xor_sync(0xffffffffu, sx, off);
        sy += __shfl_xor_sync(0xffffffffu, sy, off);
        sz += __shfl_xor_sync(0xffffffffu, sz, off);
    }
    float rK;
    asm("rcp.approx.f32 %0, %1;" : "=f"(rK) : "f"((float)K));
    const float mx = sx * rK, my = sy * rK, mz = sz * rK;

    // pad invalid rows with a COPY of row 0 (K>=1 always): duplicates a valid
    // point's d-value, so min/max are unaffected by padding.
    float r0x = __shfl_sync(0xffffffffu, row.x, 0);
    float r0y = __shfl_sync(0xffffffffu, row.y, 0);
    float r0z = __shfl_sync(0xffffffffu, row.z, 0);
    float r0w = __shfl_sync(0xffffffffu, row.w, 0);
    if (lane >= K) { row.x = r0x; row.y = r0y; row.z = r0z; row.w = r0w; }
    sdat[lp][0][lane] = row.x;
    sdat[lp][1][lane] = row.y;
    sdat[lp][2][lane] = row.z;
    sdat[lp][3][lane] = row.w;
    __syncwarp();

    // ---- per-thread constants: channels (2*lane, 2*lane+1) ----
    const float2 A0 = g_pA[0][lane], A1 = g_pA[1][lane];
    const float2 A2 = g_pA[2][lane], A3 = g_pA[3][lane];
    const float2 M4 = g_pW[0][lane], M5 = g_pW[1][lane], M6 = g_pW[2][lane];
    const float2 C7 = g_pW[3][lane], C8 = g_pW[4][lane], C9 = g_pW[5][lane];
    const float2 bp = g_pbp[lane],   gb = g_pgb[lane];

    const int4 cr = coors[p];
    const float czf = (float)cr.x;   // coors[:,0] = cz
    const float cyf = (float)cr.y;   // coors[:,1] = cy
    const float cxf = (float)cr.z;   // coors[:,2] = cx

    float cst0 = bp.x, cst1 = bp.y;
    cst0 = fmaf(mx,  M4.x, cst0); cst1 = fmaf(mx,  M4.y, cst1);
    cst0 = fmaf(my,  M5.x, cst0); cst1 = fmaf(my,  M5.y, cst1);
    cst0 = fmaf(mz,  M6.x, cst0); cst1 = fmaf(mz,  M6.y, cst1);
    cst0 = fmaf(cxf, C7.x, cst0); cst1 = fmaf(cxf, C7.y, cst1);
    cst0 = fmaf(cyf, C8.x, cst0); cst1 = fmaf(cyf, C8.y, cst1);
    cst0 = fmaf(czf, C9.x, cst0); cst1 = fmaf(czf, C9.y, cst1);

    // duplicated packed coefficients (built once; used every iter)
    const u64 a0c0 = pack2(A0.x, A0.x), a0c1 = pack2(A0.y, A0.y);
    const u64 a1c0 = pack2(A1.x, A1.x), a1c1 = pack2(A1.y, A1.y);
    const u64 a2c0 = pack2(A2.x, A2.x), a2c1 = pack2(A2.y, A2.y);
    const u64 a3c0 = pack2(A3.x, A3.x), a3c1 = pack2(A3.y, A3.y);

    const float INF = 3.402823466e38f;
    float mx0a = -INF, mx0b = -INF, mn0a = INF, mn0b = INF;   // channel 0
    float mx1a = -INF, mx1b = -INF, mn1a = INF, mn1b = INF;   // channel 1

    const int T = (K + 3) >> 2;
#pragma unroll 2
    for (int i = 0; i < T; i++) {
        // 4 points of each component as (m,m+1),(m+2,m+3) f32x2 pairs
        ulonglong2 X  = *(const ulonglong2*)&sdat[lp][0][4 * i];
        ulonglong2 Y  = *(const ulonglong2*)&sdat[lp][1][4 * i];
        ulonglong2 Z  = *(const ulonglong2*)&sdat[lp][2][4 * i];
        ulonglong2 Wv = *(const ulonglong2*)&sdat[lp][3][4 * i];

        // channel 0
        u64 d0a = fma2(X.x, a0c0, fma2(Y.x, a1c0, fma2(Z.x, a2c0, mul2(Wv.x, a3c0))));
        u64 d0b = fma2(X.y, a0c0, fma2(Y.y, a1c0, fma2(Z.y, a2c0, mul2(Wv.y, a3c0))));
        // channel 1
        u64 d1a = fma2(X.x, a0c1, fma2(Y.x, a1c1, fma2(Z.x, a2c1, mul2(Wv.x, a3c1))));
        u64 d1b = fma2(X.y, a0c1, fma2(Y.y, a1c1, fma2(Z.y, a2c1, mul2(Wv.y, a3c1))));

        float l, h;
        unpack2(d0a, l, h); mx0a = fmaxf(mx0a, l); mn0a = fminf(mn0a, l);
                            mx0b = fmaxf(mx0b, h); mn0b = fminf(mn0b, h);
        unpack2(d0b, l, h); mx0a = fmaxf(mx0a, l); mn0a = fminf(mn0a, l);
                            mx0b = fmaxf(mx0b, h); mn0b = fminf(mn0b, h);
        unpack2(d1a, l, h); mx1a = fmaxf(mx1a, l); mn1a = fminf(mn1a, l);
                            mx1b = fmaxf(mx1b, h); mn1b = fminf(mn1b, h);
        unpack2(d1b, l, h); mx1a = fmaxf(mx1a, l); mn1a = fminf(mn1a, l);
                            mx1b = fmaxf(mx1b, h); mn1b = fminf(mn1b, h);
    }

    const float dmax0 = fmaxf(mx0a, mx0b), dmin0 = fminf(mn0a, mn0b);
    const float dmax1 = fmaxf(mx1a, mx1b), dmin1 = fminf(mn1a, mn1b);

    // gelu unimodal => max over gelu = max(gelu(min), gelu(max));
    // masked rows contribute exactly gelu(true bias).
    float r0 = fmaxf(gelu_fast(dmax0 + cst0), gelu_fast(dmin0 + cst0));
    float r1 = fmaxf(gelu_fast(dmax1 + cst1), gelu_fast(dmin1 + cst1));
    if (K < MPTS) { r0 = fmaxf(r0, gb.x); r1 = fmaxf(r1, gb.y); }

    *(float2*)&out[(size_t)p * 64 + 2 * lane] = make_float2(r0, r1);
}

extern "C" void kernel_launch(void* const* d_in, const int* in_sizes, int n_in,
                              void* d_out, int out_size) {
    const float* features   = (const float*)d_in[0];
    const int*   num_points = (const int*)d_in[1];
    const int*   coors      = (const int*)d_in[2];
    const float* W          = (const float*)d_in[3];
    const float* gamma      = (const float*)d_in[4];
    const float* beta       = (const float*)d_in[5];
    const float* rmean      = (const float*)d_in[6];
    const float* rvar       = (const float*)d_in[7];
    float* out = (float*)d_out;

    const int N = in_sizes[0] / (MPTS * 4);

    pfn_precompute<<<1, 64>>>(W, gamma, beta, rmean, rvar);

    int blocks = (N + PPB - 1) / PPB;
    pfn_main<<<blocks, PPB * 32>>>((const float4*)features, num_points,
                                   (const int4*)coors, out, N);
}

// round 14
// speedup vs baseline: 1.2070x; 1.0419x over previous
#include <cuda_runtime.h>
#include <math.h>

#define MPTS 32
#define PPB  2     // pillars per block, 1 warp per pillar (64 threads)

// Precomputed constants, packed per channel-pair t: (val[2t], val[2t+1])
__device__ float2 g_pA[4][32];   // folded A0..A3 (dot coefficients)
__device__ float2 g_pW[6][32];   // -W4..-W6 (mean terms), C7..C9 (coor terms)
__device__ float2 g_pbp[32];     // cst-chain bias (voxel offsets folded in)
__device__ float2 g_pgb[32];     // gelu(true bias) = masked-row contribution

__device__ __forceinline__ float gelu_exact(float x) {
    return 0.5f * x * (1.0f + erff(x * 0.70710678118654752f));
}

// Branchless fast GELU: erf via Abramowitz-Stegun 7.1.26 (|err| < 1.5e-7).
// Tails are exact: exp2 underflows to 0 => gelu -> x (x>0) / 0 (x<0).
__device__ __forceinline__ float gelu_fast(float x) {
    float t = fabsf(x) * 0.70710678118654752f;
    float kd = fmaf(0.3275911f, t, 1.0f);
    float k;
    asm("rcp.approx.f32 %0, %1;" : "=f"(k) : "f"(kd));
    float p = fmaf(1.061405429f, k, -1.453152027f);
    p = fmaf(p, k, 1.421413741f);
    p = fmaf(p, k, -0.284496736f);
    p = fmaf(p, k, 0.254829592f);
    p = p * k;
    float e = exp2f(-t * t * 1.4426950408889634f);   // exp(-t^2)
    float erf_abs = fmaf(-p, e, 1.0f);                // erf(|x|/sqrt2)
    float erf_x = copysignf(erf_abs, x);
    float hx = 0.5f * x;
    return fmaf(hx, erf_x, hx);                       // 0.5*x*(1+erf)
}

typedef unsigned long long u64;
__device__ __forceinline__ u64 fma2(u64 a, u64 b, u64 c) {
    u64 d; asm("fma.rn.f32x2 %0, %1, %2, %3;" : "=l"(d) : "l"(a), "l"(b), "l"(c));
    return d;
}
__device__ __forceinline__ u64 mul2(u64 a, u64 b) {
    u64 d; asm("mul.rn.f32x2 %0, %1, %2;" : "=l"(d) : "l"(a), "l"(b));
    return d;
}
__device__ __forceinline__ u64 add2(u64 a, u64 b) {
    u64 d; asm("add.rn.f32x2 %0, %1, %2;" : "=l"(d) : "l"(a), "l"(b));
    return d;
}
__device__ __forceinline__ u64 pack2(float lo, float hi) {
    u64 d; asm("mov.b64 %0, {%1, %2};" : "=l"(d) : "f"(lo), "f"(hi));
    return d;
}
__device__ __forceinline__ void unpack2(u64 v, float& lo, float& hi) {
    asm("mov.b64 {%0, %1}, %2;" : "=f"(lo), "=f"(hi) : "l"(v));
}

// Fold BN into W; exploit affine structure of augmented channels:
//   x[m,o] = f0*(w0+w4+w7)+f1*(w1+w5+w8)+f2*(w2+w6+w9)+f3*w3
//            - mx*w4-my*w5-mz*w6 - px*w7-py*w8-pz*w9 + bias
// Voxel-center terms folded: -px*w7 = cx*(-0.2*w7) - 0.1*w7 (offset into bp').
__global__ void pfn_precompute(const float* __restrict__ W,
                               const float* __restrict__ gamma,
                               const float* __restrict__ beta,
                               const float* __restrict__ rmean,
                               const float* __restrict__ rvar) {
    int o = threadIdx.x;
    if (o >= 64) return;
    float s  = rsqrtf(rvar[o] + 1e-3f) * gamma[o];
    float bp = beta[o] - rmean[o] * s;      // true BN bias (masked-row value)
    float w[10];
#pragma unroll
    for (int c = 0; c < 10; c++) w[c] = W[o * 10 + c] * s;
    int t = o >> 1, h = o & 1;
    ((float*)&g_pA[0][t])[h] = w[0] + w[4] + w[7];
    ((float*)&g_pA[1][t])[h] = w[1] + w[5] + w[8];
    ((float*)&g_pA[2][t])[h] = w[2] + w[6] + w[9];
    ((float*)&g_pA[3][t])[h] = w[3];
    ((float*)&g_pW[0][t])[h] = -w[4];
    ((float*)&g_pW[1][t])[h] = -w[5];
    ((float*)&g_pW[2][t])[h] = -w[6];
    ((float*)&g_pW[3][t])[h] = -0.2f * w[7];
    ((float*)&g_pW[4][t])[h] = -0.2f * w[8];
    ((float*)&g_pW[5][t])[h] = -4.0f * w[9];
    ((float*)&g_pbp[t])[h] = bp - 0.1f * w[7] + 39.9f * w[8] + 1.0f * w[9];
    ((float*)&g_pgb[t])[h] = gelu_exact(bp);
}

// compute the 4 packed dot values for point group i
#define COMPUTE_D(i, d0a, d0b, d1a, d1b)                                        \
    {                                                                           \
        ulonglong2 X  = *(const ulonglong2*)&sdat[lp][0][4 * (i)];              \
        ulonglong2 Y  = *(const ulonglong2*)&sdat[lp][1][4 * (i)];              \
        ulonglong2 Z  = *(const ulonglong2*)&sdat[lp][2][4 * (i)];              \
        ulonglong2 Wv = *(const ulonglong2*)&sdat[lp][3][4 * (i)];              \
        d0a = fma2(X.x, a0c0, fma2(Y.x, a1c0, fma2(Z.x, a2c0, mul2(Wv.x, a3c0)))); \
        d0b = fma2(X.y, a0c0, fma2(Y.y, a1c0, fma2(Z.y, a2c0, mul2(Wv.y, a3c0)))); \
        d1a = fma2(X.x, a0c1, fma2(Y.x, a1c1, fma2(Z.x, a2c1, mul2(Wv.x, a3c1)))); \
        d1b = fma2(X.y, a0c1, fma2(Y.y, a1c1, fma2(Z.y, a2c1, mul2(Wv.y, a3c1)))); \
    }

__global__ __launch_bounds__(PPB * 32)
void pfn_main(const float4* __restrict__ feats,      // [N,32] float4
              const int*    __restrict__ num_points,  // [N]
              const int4*   __restrict__ coors,       // [N] (z,y,x,_)
              float*        __restrict__ out,         // [N,64]
              int N) {
    __shared__ float sdat[PPB][4][MPTS];   // transposed SoA per pillar

    const int lp   = threadIdx.x >> 5;
    const int lane = threadIdx.x & 31;
    const int p    = blockIdx.x * PPB + lp;
    if (p >= N) return;                     // whole warp exits together

    const int K = num_points[p];

    // ---- stage: coalesced 512B row load per warp ----
    float4 row = feats[(size_t)p * MPTS + lane];

    // mean over ALL 32 raw rows (reference sums unmasked garbage too), / K.
    // x,y reduced as one packed f32x2 (identical add order to scalar tree).
    u64 sxy = pack2(row.x, row.y);
    float szf = row.z;
#pragma unroll
    for (int off = 16; off; off >>= 1) {
        sxy = add2(sxy, __shfl_xor_sync(0xffffffffu, sxy, off));
        szf += __shfl_xor_sync(0xffffffffu, szf, off);
    }
    float sx, sy;
    unpack2(sxy, sx, sy);
    float rK;
    asm("rcp.approx.f32 %0, %1;" : "=f"(rK) : "f"((float)K));
    const float mx = sx * rK, my = sy * rK, mz = szf * rK;

    // pad invalid rows with a COPY of row 0 (K>=1 always): duplicates a valid
    // point's d-value, so min/max are unaffected by padding.
    float r0x = __shfl_sync(0xffffffffu, row.x, 0);
    float r0y = __shfl_sync(0xffffffffu, row.y, 0);
    float r0z = __shfl_sync(0xffffffffu, row.z, 0);
    float r0w = __shfl_sync(0xffffffffu, row.w, 0);
    if (lane >= K) { row.x = r0x; row.y = r0y; row.z = r0z; row.w = r0w; }
    sdat[lp][0][lane] = row.x;
    sdat[lp][1][lane] = row.y;
    sdat[lp][2][lane] = row.z;
    sdat[lp][3][lane] = row.w;
    __syncwarp();

    // ---- per-thread constants: channels (2*lane, 2*lane+1) ----
    const float2 A0 = g_pA[0][lane], A1 = g_pA[1][lane];
    const float2 A2 = g_pA[2][lane], A3 = g_pA[3][lane];
    const float2 M4 = g_pW[0][lane], M5 = g_pW[1][lane], M6 = g_pW[2][lane];
    const float2 C7 = g_pW[3][lane], C8 = g_pW[4][lane], C9 = g_pW[5][lane];
    const float2 bp = g_pbp[lane],   gb = g_pgb[lane];

    const int4 cr = coors[p];
    const float czf = (float)cr.x;   // coors[:,0] = cz
    const float cyf = (float)cr.y;   // coors[:,1] = cy
    const float cxf = (float)cr.z;   // coors[:,2] = cx

    float cst0 = bp.x, cst1 = bp.y;
    cst0 = fmaf(mx,  M4.x, cst0); cst1 = fmaf(mx,  M4.y, cst1);
    cst0 = fmaf(my,  M5.x, cst0); cst1 = fmaf(my,  M5.y, cst1);
    cst0 = fmaf(mz,  M6.x, cst0); cst1 = fmaf(mz,  M6.y, cst1);
    cst0 = fmaf(cxf, C7.x, cst0); cst1 = fmaf(cxf, C7.y, cst1);
    cst0 = fmaf(cyf, C8.x, cst0); cst1 = fmaf(cyf, C8.y, cst1);
    cst0 = fmaf(czf, C9.x, cst0); cst1 = fmaf(czf, C9.y, cst1);

    // duplicated packed coefficients (built once; used every iter)
    const u64 a0c0 = pack2(A0.x, A0.x), a0c1 = pack2(A0.y, A0.y);
    const u64 a1c0 = pack2(A1.x, A1.x), a1c1 = pack2(A1.y, A1.y);
    const u64 a2c0 = pack2(A2.x, A2.x), a2c1 = pack2(A2.y, A2.y);
    const u64 a3c0 = pack2(A3.x, A3.x), a3c1 = pack2(A3.y, A3.y);

    // ---- peeled first group (K>=1 => T>=1): d-values INITIALIZE the
    // accumulators, saving 8 init MOVs + 8 FMNMX vs folding into +-INF ----
    float mx0a, mx0b, mn0a, mn0b, mx1a, mx1b, mn1a, mn1b;
    {
        u64 d0a, d0b, d1a, d1b;
        COMPUTE_D(0, d0a, d0b, d1a, d1b)
        float la, ha, lb, hb;
        unpack2(d0a, la, ha); unpack2(d0b, lb, hb);
        mx0a = fmaxf(la, lb); mn0a = fminf(la, lb);
        mx0b = fmaxf(ha, hb); mn0b = fminf(ha, hb);
        unpack2(d1a, la, ha); unpack2(d1b, lb, hb);
        mx1a = fmaxf(la, lb); mn1a = fminf(la, lb);
        mx1b = fmaxf(ha, hb); mn1b = fminf(ha, hb);
    }

    const int T = (K + 3) >> 2;
#pragma unroll 2
    for (int i = 1; i < T; i++) {
        u64 d0a, d0b, d1a, d1b;
        COMPUTE_D(i, d0a, d0b, d1a, d1b)

        float l, h;
        unpack2(d0a, l, h); mx0a = fmaxf(mx0a, l); mn0a = fminf(mn0a, l);
                            mx0b = fmaxf(mx0b, h); mn0b = fminf(mn0b, h);
        unpack2(d0b, l, h); mx0a = fmaxf(mx0a, l); mn0a = fminf(mn0a, l);
                            mx0b = fmaxf(mx0b, h); mn0b = fminf(mn0b, h);
        unpack2(d1a, l, h); mx1a = fmaxf(mx1a, l); mn1a = fminf(mn1a, l);
                            mx1b = fmaxf(mx1b, h); mn1b = fminf(mn1b, h);
        unpack2(d1b, l, h); mx1a = fmaxf(mx1a, l); mn1a = fminf(mn1a, l);
                            mx1b = fmaxf(mx1b, h); mn1b = fminf(mn1b, h);
    }

    const float dmax0 = fmaxf(mx0a, mx0b), dmin0 = fminf(mn0a, mn0b);
    const float dmax1 = fmaxf(mx1a, mx1b), dmin1 = fminf(mn1a, mn1b);

    // gelu unimodal => max over gelu = max(gelu(min), gelu(max));
    // masked rows contribute exactly gelu(true bias).
    float r0 = fmaxf(gelu_fast(dmax0 + cst0), gelu_fast(dmin0 + cst0));
    float r1 = fmaxf(gelu_fast(dmax1 + cst1), gelu_fast(dmin1 + cst1));
    if (K < MPTS) { r0 = fmaxf(r0, gb.x); r1 = fmaxf(r1, gb.y); }

    *(float2*)&out[(size_t)p * 64 + 2 * lane] = make_float2(r0, r1);
}

extern "C" void kernel_launch(void* const* d_in, const int* in_sizes, int n_in,
                              void* d_out, int out_size) {
    const float* features   = (const float*)d_in[0];
    const int*   num_points = (const int*)d_in[1];
    const int*   coors      = (const int*)d_in[2];
    const float* W          = (const float*)d_in[3];
    const float* gamma      = (const float*)d_in[4];
    const float* beta       = (const float*)d_in[5];
    const float* rmean      = (const float*)d_in[6];
    const float* rvar       = (const float*)d_in[7];
    float* out = (float*)d_out;

    const int N = in_sizes[0] / (MPTS * 4);

    pfn_precompute<<<1, 64>>>(W, gamma, beta, rmean, rvar);

    int blocks = (N + PPB - 1) / PPB;
    pfn_main<<<blocks, PPB * 32>>>((const float4*)features, num_points,
                                   (const int4*)coors, out, N);
}